// round 7
// baseline (speedup 1.0000x reference)
#include <cuda_runtime.h>

#define Nn 16384
#define EE 524288
#define PADDED (EE + 3*Nn + 8)
#define CIN 128
#define HH 64
#define KK 64
#define NT 1024

typedef unsigned long long u64;

// ---------------- device scratch (zero-restore invariant) ----------------
__device__ __align__(16) float g_xw[Nn*HH];
__device__ __align__(16) float g_h[Nn*HH];
__device__ float g_dis[Nn];
__device__ float g_deg[Nn];                 // 0 at entry; zeroed in PD
__device__ int   g_cnt[Nn];                 // 0 at entry; zeroed in PH
__device__ int   g_off[Nn];                 // padded CSC starts (mult of 4)
__device__ int   g_cur[Nn];
__device__ __align__(16) u64  g_ed[PADDED];   // (wn_bits<<32)|row
__device__ __align__(16) int  g_rows[PADDED]; // row only (for trace)
__device__ __align__(16) float g_W[HH*KK];
__device__ float g_bb[KK];
__device__ float g_ss[KK*KK];               // zeroed in PH
__device__ float g_ca[KK];                  // zeroed in PH
__device__ float g_cs[KK];                  // zeroed in PH
__device__ double g_trace;                  // zeroed in PH
__device__ unsigned g_bar_cnt, g_bar_gen;
__device__ unsigned g_ws0, g_ws1, g_ws2, g_ws3;

// ---------------- f32x2 helpers ----------------
__device__ __forceinline__ u64 pk2(float a, float b) {
    u64 r; asm("mov.b64 %0,{%1,%2};" : "=l"(r) : "f"(a), "f"(b)); return r;
}
__device__ __forceinline__ u64 bc2(float a) { return pk2(a, a); }
__device__ __forceinline__ void fma2(u64& d, u64 a, u64 b) {
    asm("fma.rn.f32x2 %0,%1,%2,%0;" : "+l"(d) : "l"(a), "l"(b));
}
__device__ __forceinline__ float2 up2(u64 v) {
    float2 f; asm("mov.b64 {%0,%1},%2;" : "=f"(f.x), "=f"(f.y) : "l"(v)); return f;
}
__device__ __forceinline__ float hsum2(u64 v) { float2 f = up2(v); return f.x + f.y; }

__device__ __forceinline__ void gsync() {
    __syncthreads();
    if (threadIdx.x == 0) {
        volatile unsigned* genp = &g_bar_gen;
        unsigned gen = *genp;
        __threadfence();
        if (atomicAdd(&g_bar_cnt, 1u) == gridDim.x - 1) {
            g_bar_cnt = 0;
            __threadfence();
            atomicAdd(&g_bar_gen, 1u);
        } else {
            while (*genp == gen) __nanosleep(32);
        }
        __threadfence();
    }
    __syncthreads();
}

__global__ void __launch_bounds__(NT, 1)
mega(const float* __restrict__ x, const int* __restrict__ ei,
     const float* __restrict__ ew,
     const float* __restrict__ W1, const float* __restrict__ b1,
     const float* __restrict__ Wm1, const float* __restrict__ bm1,
     const float* __restrict__ Wm2, const float* __restrict__ bm2,
     float* __restrict__ out, int E, int out_size)
{
    __shared__ __align__(16) float shbuf[8704];   // 34 KB
    __shared__ float tr_part;
    const int tid = threadIdx.x, bid = blockIdx.x;
    const int nth = gridDim.x * NT;
    const int gt = bid * NT + tid;
    const int lane = tid & 31, wid = tid >> 5;
    const int l16 = lane & 15;
    const unsigned hmask = 0xFFFFu << (lane & 16);
    const int hsrc = lane & 16;

    // ============ PB: edge histogram + W-collapse + xw GEMM (stolen) ============
    for (int j = tid; j < CIN*HH; j += NT)
        shbuf[(j & 63) * 132 + (j >> 6)] = W1[j];

    for (int e = gt; e < E; e += nth) {
        int c = __ldg(ei + E + e);
        atomicAdd(&g_deg[c], __ldg(ew + e));
        atomicAdd(&g_cnt[c], 1);
    }

    if (bid == 0) {
        int a = tid >> 4;
        int c0 = (tid & 15) * 4;
        float4 acc = make_float4(0.f, 0.f, 0.f, 0.f);
        #pragma unroll 8
        for (int j = 0; j < HH; j++) {
            float m = __ldg(Wm1 + a*HH + j);
            float4 w2 = __ldg((const float4*)(Wm2 + j*KK + c0));
            acc.x += m * w2.x; acc.y += m * w2.y;
            acc.z += m * w2.z; acc.w += m * w2.w;
        }
        ((float4*)g_W)[tid] = acc;
        if (tid < KK) {
            float b = __ldg(bm2 + tid);
            for (int j = 0; j < HH; j++) b += __ldg(bm1 + j) * __ldg(Wm2 + j*KK + tid);
            g_bb[tid] = b;
        }
    }
    __syncthreads();

    // xw GEMM (f32x2): warp steals chunks of 4 rows
    {
        const float* wp0 = shbuf + lane * 132;
        const float* wp1 = shbuf + (lane + 32) * 132;
        for (;;) {
            int p = 0;
            if (lane == 0) p = (int)atomicAdd(&g_ws2, 1u);
            p = __shfl_sync(0xFFFFFFFFu, p, 0);
            int r0 = p * 4;
            if (r0 >= Nn) break;
            u64 A0=0,A1=0,A2=0,A3=0,A4=0,A5=0,A6=0,A7=0;
            const float* x0 = x + (size_t)r0 * CIN;
            #pragma unroll 4
            for (int k = 0; k < CIN; k += 4) {
                ulonglong2 w0 = *(const ulonglong2*)(wp0 + k);
                ulonglong2 w1 = *(const ulonglong2*)(wp1 + k);
                ulonglong2 xa = *(const ulonglong2*)(x0 + k);
                ulonglong2 xb = *(const ulonglong2*)(x0 + CIN + k);
                ulonglong2 xc = *(const ulonglong2*)(x0 + 2*CIN + k);
                ulonglong2 xd = *(const ulonglong2*)(x0 + 3*CIN + k);
                fma2(A0, xa.x, w0.x); fma2(A0, xa.y, w0.y);
                fma2(A1, xa.x, w1.x); fma2(A1, xa.y, w1.y);
                fma2(A2, xb.x, w0.x); fma2(A2, xb.y, w0.y);
                fma2(A3, xb.x, w1.x); fma2(A3, xb.y, w1.y);
                fma2(A4, xc.x, w0.x); fma2(A4, xc.y, w0.y);
                fma2(A5, xc.x, w1.x); fma2(A5, xc.y, w1.y);
                fma2(A6, xd.x, w0.x); fma2(A6, xd.y, w0.y);
                fma2(A7, xd.x, w1.x); fma2(A7, xd.y, w1.y);
            }
            float* o = g_xw + (size_t)r0 * HH;
            o[lane] = hsum2(A0);        o[lane+32] = hsum2(A1);
            o[HH+lane] = hsum2(A2);     o[HH+lane+32] = hsum2(A3);
            o[2*HH+lane] = hsum2(A4);   o[2*HH+lane+32] = hsum2(A5);
            o[3*HH+lane] = hsum2(A6);   o[3*HH+lane+32] = hsum2(A7);
        }
    }
    gsync();

    // ============ PC: block0 scan (4-aligned padded counts) || others dis ============
    if (bid == 0) {
        int* wsum = (int*)shbuf;
        int base = tid * 16;
        int local[16];
        int s = 0;
        #pragma unroll
        for (int i = 0; i < 16; i++) {
            int cc = g_cnt[base + i];
            local[i] = (cc + 3) & ~3;      // pad each bucket to multiple of 4
            s += local[i];
        }
        int ws = s;
        #pragma unroll
        for (int o = 1; o < 32; o <<= 1) {
            int v = __shfl_up_sync(0xFFFFFFFFu, ws, o);
            if (lane >= o) ws += v;
        }
        if (lane == 31) wsum[wid] = ws;
        __syncthreads();
        if (tid < 32) {
            int v = wsum[tid];
            #pragma unroll
            for (int o = 1; o < 32; o <<= 1) {
                int u = __shfl_up_sync(0xFFFFFFFFu, v, o);
                if (tid >= o) v += u;
            }
            wsum[tid] = v;
        }
        __syncthreads();
        int run = (wid ? wsum[wid - 1] : 0) + ws - s;
        #pragma unroll
        for (int i = 0; i < 16; i++) {
            g_off[base + i] = run;
            g_cur[base + i] = run;
            run += local[i];
        }
    } else {
        for (int j = (bid - 1) * NT + tid; j < Nn; j += (gridDim.x - 1) * NT)
            g_dis[j] = rsqrtf(g_deg[j] + 1.0f);   // +1 self loop
    }
    gsync();

    // ============ PD: fill buckets + restore deg/ws2 ============
    for (int j = gt; j < Nn; j += nth) g_deg[j] = 0.f;
    if (gt == 0) g_ws2 = 0u;
    for (int e = gt; e < E; e += nth) {
        int r = __ldg(ei + e);
        int c = __ldg(ei + E + e);
        float wn = g_dis[r] * __ldg(ew + e) * g_dis[c];
        int pos = atomicAdd(&g_cur[c], 1);
        g_ed[pos] = ((u64)__float_as_uint(wn) << 32) | (unsigned)r;
        g_rows[pos] = r;
    }
    gsync();

    // ============ PE: gather + self loop + bias + relu (steal, f32x2) ============
    {
        const float* xwb = g_xw;
        float4 bb = __ldg((const float4*)b1 + l16);
        for (;;) {
            int p = 0;
            if (l16 == 0) p = (int)atomicAdd(&g_ws0, 1u);
            int c = __shfl_sync(hmask, p, hsrc);
            if (c >= Nn) break;
            int beg = g_off[c];
            int end = beg + g_cnt[c];
            float dc = g_dis[c];
            float sw = dc * dc;
            float4 sv = *(const float4*)(xwb + c*64 + l16*4);
            u64 a0 = pk2(sv.x*sw, sv.y*sw);
            u64 a1 = pk2(sv.z*sw, sv.w*sw);
            int j = beg;
            for (; j + 8 <= end; j += 8) {
                ulonglong2 e0 = *(const ulonglong2*)(g_ed + j);
                ulonglong2 e1 = *(const ulonglong2*)(g_ed + j + 2);
                ulonglong2 e2 = *(const ulonglong2*)(g_ed + j + 4);
                ulonglong2 e3 = *(const ulonglong2*)(g_ed + j + 6);
                // group 1
                int r0 = (int)(unsigned)e0.x, r1 = (int)(unsigned)e0.y;
                int r2 = (int)(unsigned)e1.x, r3 = (int)(unsigned)e1.y;
                u64 W0 = bc2(__uint_as_float((unsigned)(e0.x >> 32)));
                u64 W1v = bc2(__uint_as_float((unsigned)(e0.y >> 32)));
                u64 W2 = bc2(__uint_as_float((unsigned)(e1.x >> 32)));
                u64 W3 = bc2(__uint_as_float((unsigned)(e1.y >> 32)));
                ulonglong2 v0 = *(const ulonglong2*)(xwb + r0*64 + l16*4);
                ulonglong2 v1 = *(const ulonglong2*)(xwb + r1*64 + l16*4);
                ulonglong2 v2 = *(const ulonglong2*)(xwb + r2*64 + l16*4);
                ulonglong2 v3 = *(const ulonglong2*)(xwb + r3*64 + l16*4);
                fma2(a0, W0, v0.x); fma2(a1, W0, v0.y);
                fma2(a0, W1v, v1.x); fma2(a1, W1v, v1.y);
                fma2(a0, W2, v2.x); fma2(a1, W2, v2.y);
                fma2(a0, W3, v3.x); fma2(a1, W3, v3.y);
                // group 2
                int r4 = (int)(unsigned)e2.x, r5 = (int)(unsigned)e2.y;
                int r6 = (int)(unsigned)e3.x, r7 = (int)(unsigned)e3.y;
                u64 W4 = bc2(__uint_as_float((unsigned)(e2.x >> 32)));
                u64 W5 = bc2(__uint_as_float((unsigned)(e2.y >> 32)));
                u64 W6 = bc2(__uint_as_float((unsigned)(e3.x >> 32)));
                u64 W7 = bc2(__uint_as_float((unsigned)(e3.y >> 32)));
                ulonglong2 v4 = *(const ulonglong2*)(xwb + r4*64 + l16*4);
                ulonglong2 v5 = *(const ulonglong2*)(xwb + r5*64 + l16*4);
                ulonglong2 v6 = *(const ulonglong2*)(xwb + r6*64 + l16*4);
                ulonglong2 v7 = *(const ulonglong2*)(xwb + r7*64 + l16*4);
                fma2(a0, W4, v4.x); fma2(a1, W4, v4.y);
                fma2(a0, W5, v5.x); fma2(a1, W5, v5.y);
                fma2(a0, W6, v6.x); fma2(a1, W6, v6.y);
                fma2(a0, W7, v7.x); fma2(a1, W7, v7.y);
            }
            for (; j < end; j++) {
                u64 e = g_ed[j];
                int r = (int)(unsigned)e;
                u64 W = bc2(__uint_as_float((unsigned)(e >> 32)));
                ulonglong2 v = *(const ulonglong2*)(xwb + r*64 + l16*4);
                fma2(a0, W, v.x); fma2(a1, W, v.y);
            }
            float2 pa = up2(a0), pb = up2(a1);
            float4 o;
            o.x = fmaxf(pa.x + bb.x, 0.f);
            o.y = fmaxf(pa.y + bb.y, 0.f);
            o.z = fmaxf(pb.x + bb.z, 0.f);
            o.w = fmaxf(pb.y + bb.w, 0.f);
            *(float4*)(g_h + c*64 + l16*4) = o;
        }
        __syncwarp();
    }
    gsync();

    // ============ PF: collapsed MLP + softmax + cs/ca (steal, f32x2) ============
    {
        if (gt == 0) g_ws0 = 0u;
        for (int j = tid; j < HH*KK; j += NT)
            shbuf[(j & 63) * 68 + (j >> 6)] = g_W[j];
        __syncthreads();
        const float* wp0 = shbuf + lane * 68;
        const float* wp1 = shbuf + (lane + 32) * 68;
        float b2a = g_bb[lane], b2b = g_bb[lane + 32];
        float cs0 = 0.f, cs1 = 0.f, ca0 = 0.f, ca1 = 0.f;
        for (;;) {
            int p = 0;
            if (lane == 0) p = (int)atomicAdd(&g_ws3, 1u);
            p = __shfl_sync(0xFFFFFFFFu, p, 0);
            int r0 = p * 2;
            if (r0 >= Nn) break;
            const float* h0 = g_h + (size_t)r0 * HH;
            const float* h1 = h0 + HH;
            u64 L00=0, L01=0, L10=0, L11=0;
            #pragma unroll 4
            for (int k = 0; k < HH; k += 4) {
                ulonglong2 wa = *(const ulonglong2*)(wp0 + k);
                ulonglong2 wb = *(const ulonglong2*)(wp1 + k);
                ulonglong2 ha = *(const ulonglong2*)(h0 + k);
                ulonglong2 hb = *(const ulonglong2*)(h1 + k);
                fma2(L00, ha.x, wa.x); fma2(L00, ha.y, wa.y);
                fma2(L01, ha.x, wb.x); fma2(L01, ha.y, wb.y);
                fma2(L10, hb.x, wa.x); fma2(L10, hb.y, wa.y);
                fma2(L11, hb.x, wb.x); fma2(L11, hb.y, wb.y);
            }
            float l00 = b2a + hsum2(L00), l01 = b2b + hsum2(L01);
            float l10 = b2a + hsum2(L10), l11 = b2b + hsum2(L11);
            float mx0 = fmaxf(l00, l01);
            float mx1 = fmaxf(l10, l11);
            #pragma unroll
            for (int o = 16; o; o >>= 1) {
                mx0 = fmaxf(mx0, __shfl_xor_sync(0xFFFFFFFFu, mx0, o));
                mx1 = fmaxf(mx1, __shfl_xor_sync(0xFFFFFFFFu, mx1, o));
            }
            float e00 = __expf(l00 - mx0), e01 = __expf(l01 - mx0);
            float e10 = __expf(l10 - mx1), e11 = __expf(l11 - mx1);
            float sm0 = e00 + e01, sm1 = e10 + e11;
            #pragma unroll
            for (int o = 16; o; o >>= 1) {
                sm0 += __shfl_xor_sync(0xFFFFFFFFu, sm0, o);
                sm1 += __shfl_xor_sync(0xFFFFFFFFu, sm1, o);
            }
            float i0 = 1.0f / sm0, i1 = 1.0f / sm1;
            float s00 = e00 * i0, s01 = e01 * i0;
            float s10 = e10 * i1, s11 = e11 * i1;
            out[(size_t)r0*KK + lane]          = s00;
            out[(size_t)r0*KK + lane + 32]     = s01;
            out[(size_t)(r0+1)*KK + lane]      = s10;
            out[(size_t)(r0+1)*KK + lane + 32] = s11;
            cs0 += s00 + s10; cs1 += s01 + s11;
            float da0 = (float)g_cnt[r0];
            float da1 = (float)g_cnt[r0 + 1];
            ca0 += s00 * da0 + s10 * da1;
            ca1 += s01 * da0 + s11 * da1;
        }
        atomicAdd(&g_cs[lane], cs0); atomicAdd(&g_cs[lane + 32], cs1);
        atomicAdd(&g_ca[lane], ca0); atomicAdd(&g_ca[lane + 32], ca1);
    }
    gsync();

    // ============ PG: ss = s^T s + trace (steal, f32x2) ============
    {
        if (tid == 0) tr_part = 0.f;
        if (gt == 0) g_ws3 = 0u;

        // --- ss: 16-row chunks, thread = (a, 4 cols) via f32x2 ---
        float* srows = shbuf;
        int a = tid >> 4, q = tid & 15;
        u64 S0 = 0, S1 = 0;
        for (int base = bid * 16; base < Nn; base += gridDim.x * 16) {
            __syncthreads();
            if (tid < 256) ((float4*)srows)[tid] = ((const float4*)(out + (size_t)base*KK))[tid];
            __syncthreads();
            #pragma unroll
            for (int r = 0; r < 16; r++) {
                u64 A = bc2(srows[r*KK + a]);
                ulonglong2 bv = *(const ulonglong2*)(srows + r*KK + q*4);
                fma2(S0, A, bv.x);
                fma2(S1, A, bv.y);
            }
        }
        {
            float2 f0 = up2(S0), f1 = up2(S1);
            atomicAdd(&g_ss[a*KK + q*4 + 0], f0.x);
            atomicAdd(&g_ss[a*KK + q*4 + 1], f0.y);
            atomicAdd(&g_ss[a*KK + q*4 + 2], f1.x);
            atomicAdd(&g_ss[a*KK + q*4 + 3], f1.y);
        }
        __syncthreads();

        // --- trace: half-warp per node, int4 row loads, f32x2 elementwise acc ---
        const float* sb = out;
        u64 t0 = 0, t1 = 0;
        for (;;) {
            int p = 0;
            if (l16 == 0) p = (int)atomicAdd(&g_ws1, 1u);
            int c = __shfl_sync(hmask, p, hsrc);
            if (c >= Nn) break;
            int beg = g_off[c];
            int end = beg + g_cnt[c];
            float4 scv = *(const float4*)(sb + c*64 + l16*4);
            u64 scx = pk2(scv.x, scv.y), scy = pk2(scv.z, scv.w);
            int j = beg;
            for (; j + 8 <= end; j += 8) {
                int4 ra = *(const int4*)(g_rows + j);
                int4 rb = *(const int4*)(g_rows + j + 4);
                ulonglong2 v0 = *(const ulonglong2*)(sb + ra.x*64 + l16*4);
                ulonglong2 v1 = *(const ulonglong2*)(sb + ra.y*64 + l16*4);
                ulonglong2 v2 = *(const ulonglong2*)(sb + ra.z*64 + l16*4);
                ulonglong2 v3 = *(const ulonglong2*)(sb + ra.w*64 + l16*4);
                fma2(t0, v0.x, scx); fma2(t1, v0.y, scy);
                fma2(t0, v1.x, scx); fma2(t1, v1.y, scy);
                fma2(t0, v2.x, scx); fma2(t1, v2.y, scy);
                fma2(t0, v3.x, scx); fma2(t1, v3.y, scy);
                ulonglong2 v4 = *(const ulonglong2*)(sb + rb.x*64 + l16*4);
                ulonglong2 v5 = *(const ulonglong2*)(sb + rb.y*64 + l16*4);
                ulonglong2 v6 = *(const ulonglong2*)(sb + rb.z*64 + l16*4);
                ulonglong2 v7 = *(const ulonglong2*)(sb + rb.w*64 + l16*4);
                fma2(t0, v4.x, scx); fma2(t1, v4.y, scy);
                fma2(t0, v5.x, scx); fma2(t1, v5.y, scy);
                fma2(t0, v6.x, scx); fma2(t1, v6.y, scy);
                fma2(t0, v7.x, scx); fma2(t1, v7.y, scy);
            }
            for (; j < end; j++) {
                int r = g_rows[j];
                ulonglong2 v = *(const ulonglong2*)(sb + r*64 + l16*4);
                fma2(t0, v.x, scx); fma2(t1, v.y, scy);
            }
        }
        __syncwarp();
        float tacc = hsum2(t0) + hsum2(t1);
        #pragma unroll
        for (int o = 16; o; o >>= 1) tacc += __shfl_xor_sync(0xFFFFFFFFu, tacc, o);
        if (lane == 0) atomicAdd(&tr_part, tacc);
        __syncthreads();
        if (tid == 0) atomicAdd(&g_trace, (double)tr_part);
    }
    gsync();

    // ============ PH: restore cnt + final loss (block 0) ============
    for (int j = gt; j < Nn; j += nth) g_cnt[j] = 0;
    if (bid == 0) {
        float* red = shbuf;
        float v;

        v = 0.f;
        for (int i = tid; i < KK; i += NT) v += g_ca[i] * g_ca[i];
        red[tid] = v; __syncthreads();
        for (int o = NT/2; o; o >>= 1) { if (tid < o) red[tid] += red[tid + o]; __syncthreads(); }
        float ca2 = red[0]; __syncthreads();

        v = 0.f;
        for (int i = tid; i < KK*KK; i += NT) { float u = g_ss[i]; v += u * u; }
        red[tid] = v; __syncthreads();
        for (int o = NT/2; o; o >>= 1) { if (tid < o) red[tid] += red[tid + o]; __syncthreads(); }
        float ss2 = red[0]; __syncthreads();

        v = 0.f;
        for (int i = tid; i < KK; i += NT) v += g_ss[i*KK + i];
        red[tid] = v; __syncthreads();
        for (int o = NT/2; o; o >>= 1) { if (tid < o) red[tid] += red[tid + o]; __syncthreads(); }
        float trss = red[0]; __syncthreads();

        v = 0.f;
        for (int i = tid; i < KK; i += NT) v += g_cs[i] * g_cs[i];
        red[tid] = v; __syncthreads();
        for (int o = NT/2; o; o >>= 1) { if (tid < o) red[tid] += red[tid + o]; __syncthreads(); }
        float cs2 = red[0]; __syncthreads();

        if (tid == 0) {
            float two_m = (float)E;
            float tr_out = (float)g_trace;
            float spectral = -(tr_out - ca2 / two_m) / two_m;
            float ssfro = sqrtf(ss2);
            float ortho = sqrtf(fmaxf(2.0f - trss / (4.0f * ssfro), 0.0f));
            float cluster = sqrtf(cs2) / (float)Nn * 8.0f - 1.0f;
            float loss = spectral + ortho + cluster;
            for (int i = Nn*KK; i < out_size; i++) out[i] = loss;
            g_trace = 0.0;
            g_ws1 = 0u;
        }
        __syncthreads();
        for (int i = tid; i < KK*KK; i += NT) g_ss[i] = 0.f;
        if (tid < KK) { g_ca[tid] = 0.f; g_cs[tid] = 0.f; }
    }
}

// ---------------- launch ----------------
extern "C" void kernel_launch(void* const* d_in, const int* in_sizes, int n_in,
                              void* d_out, int out_size) {
    const float* x   = (const float*)d_in[0];
    const int*   ei  = (const int*)d_in[1];
    const float* ew  = (const float*)d_in[2];
    const float* W1  = (const float*)d_in[3];
    const float* b1  = (const float*)d_in[4];
    const float* Wm1 = (const float*)d_in[5];
    const float* bm1 = (const float*)d_in[6];
    const float* Wm2 = (const float*)d_in[7];
    const float* bm2 = (const float*)d_in[8];
    float* out = (float*)d_out;
    int E = in_sizes[2];

    int nsm = 148;
    cudaDeviceGetAttribute(&nsm, cudaDevAttrMultiProcessorCount, 0);
    if (nsm < 2) nsm = 148;
    if (nsm > 512) nsm = 512;

    mega<<<nsm, NT>>>(x, ei, ew, W1, b1, Wm1, bm1, Wm2, bm2, out, E, out_size);
}